// round 1
// baseline (speedup 1.0000x reference)
#include <cuda_runtime.h>
#include <stdint.h>

#define NDU 60000
#define NDI 90000
#define NDOM (NDU + NDI)      /* 150000 */
#define NTU 200000
#define NTI 300000
#define NALL (NTU + NTI)      /* 500000 */
#define NE  2000000
#define DIM 32
#define NQ  8192

/* ---------------- static device scratch (no allocs allowed) ---------------- */
__device__ __align__(16) float g_X[(size_t)NALL * DIM];     /* 64 MB */
__device__ __align__(16) float g_A[(size_t)NALL * DIM];     /* 64 MB */
__device__ __align__(16) float g_B[(size_t)NALL * DIM];     /* 64 MB */
__device__ __align__(16) float g_light[(size_t)NDOM * DIM]; /* 19.2 MB */
__device__ __align__(16) float g_intra[(size_t)NDOM * DIM]; /* 19.2 MB */
__device__ float g_invs[NALL];
__device__ float g_w[NE];
__device__ int   g_f[2];   /* index-width flags: 1 => int64 */

/* ---------------- elementwise helpers ---------------- */
__global__ void k_zero4(float4* p, size_t n) {
    size_t i = (size_t)blockIdx.x * blockDim.x + threadIdx.x;
    if (i < n) p[i] = make_float4(0.f, 0.f, 0.f, 0.f);
}
__global__ void k_zero(float* p, int n) {
    int i = blockIdx.x * blockDim.x + threadIdx.x;
    if (i < n) p[i] = 0.f;
}
__global__ void k_copy4(float4* d, const float4* __restrict__ s, size_t n) {
    size_t i = (size_t)blockIdx.x * blockDim.x + threadIdx.x;
    if (i < n) d[i] = s[i];
}

/* degree count (float, matches segment_sum of ones) */
__global__ void k_deg(const int* __restrict__ dst, float* deg, int nE) {
    int e = blockIdx.x * blockDim.x + threadIdx.x;
    if (e < nE) atomicAdd(&deg[dst[e]], 1.0f);
}
__global__ void k_rsqrt(float* d, int n) {
    int i = blockIdx.x * blockDim.x + threadIdx.x;
    if (i < n) d[i] = rsqrtf(fmaxf(d[i], 1.0f));
}
/* per-edge symmetric norm weight */
__global__ void k_edgew(const int* __restrict__ src, const int* __restrict__ dst,
                        const float* __restrict__ invs, float* __restrict__ w, int nE) {
    int e = blockIdx.x * blockDim.x + threadIdx.x;
    if (e < nE) w[e] = invs[src[e]] * invs[dst[e]];
}

/* scatter-add propagation: 8 lanes/edge, float4 gather + red.v4 scatter */
__global__ void k_scatter(const int* __restrict__ src, const int* __restrict__ dst,
                          const float* __restrict__ w, const float* __restrict__ h,
                          float* __restrict__ agg, int nE) {
    size_t t = (size_t)blockIdx.x * blockDim.x + threadIdx.x;
    int e = (int)(t >> 3);
    int lane = (int)(t & 7);
    if (e >= nE) return;
    int s = __ldg(src + e);
    int d = __ldg(dst + e);
    float ww = __ldg(w + e);
    float4 v = *(const float4*)(h + (size_t)s * DIM + lane * 4);
    float a0 = v.x * ww, a1 = v.y * ww, a2 = v.z * ww, a3 = v.w * ww;
    float* o = agg + (size_t)d * DIM + lane * 4;
    asm volatile("red.global.add.v4.f32 [%0], {%1,%2,%3,%4};"
                 :: "l"(o), "f"(a0), "f"(a1), "f"(a2), "f"(a3) : "memory");
}

/* h = 0.9*agg + 0.1*x  (in place on agg) */
__global__ void k_final(float4* __restrict__ h, const float4* __restrict__ x, size_t n) {
    size_t i = (size_t)blockIdx.x * blockDim.x + threadIdx.x;
    if (i >= n) return;
    float4 a = h[i], b = x[i];
    a.x = 0.9f * a.x + 0.1f * b.x;
    a.y = 0.9f * a.y + 0.1f * b.y;
    a.z = 0.9f * a.z + 0.1f * b.z;
    a.w = 0.9f * a.w + 0.1f * b.w;
    h[i] = a;
}

/* light += concat(B[:NTU][uid], B[NTU:][iid]) — one float4 per thread */
__global__ void k_accum(float4* __restrict__ light, const float4* __restrict__ B,
                        const int* __restrict__ uid, const int* __restrict__ iid) {
    size_t i = (size_t)blockIdx.x * blockDim.x + threadIdx.x;
    if (i >= (size_t)NDOM * 8) return;
    int r = (int)(i >> 3);
    int c = (int)(i & 7);
    size_t sr = (r < NDU) ? (size_t)uid[r] : (size_t)NTU + (size_t)iid[r - NDU];
    float4 a = light[i], b = B[sr * 8 + c];
    a.x += b.x; a.y += b.y; a.z += b.z; a.w += b.w;
    light[i] = a;
}

/* detect int64 vs int32 index buffers: int64 (values < 2^31) => all odd words 0 */
__global__ void k_detect(const int* __restrict__ p, int nElems, int slot) {
    __shared__ int any;
    if (threadIdx.x == 0) any = 0;
    __syncthreads();
    for (int i = threadIdx.x; i < nElems / 2; i += blockDim.x)
        if (p[2 * i + 1] != 0) any = 1;
    __syncthreads();
    if (threadIdx.x == 0) g_f[slot] = (any == 0);
}

/* final: gamma[p] = dot(light_u, light_i)/9 + dot(intra_u, intra_i); one warp/pair */
__global__ void k_gamma(const void* __restrict__ users, const void* __restrict__ items,
                        const float* __restrict__ light, const float* __restrict__ intra,
                        float* __restrict__ out) {
    int p = (blockIdx.x * blockDim.x + threadIdx.x) >> 5;
    int lane = threadIdx.x & 31;
    if (p >= NQ) return;
    long long u = g_f[0] ? ((const long long*)users)[p] : (long long)((const int*)users)[p];
    long long it = g_f[1] ? ((const long long*)items)[p] : (long long)((const int*)items)[p];
    size_t ur = (size_t)u * DIM + lane;
    size_t ir = ((size_t)NDU + (size_t)it) * DIM + lane;
    float v = light[ur] * light[ir] * (1.0f / 9.0f) + intra[ur] * intra[ir];
#pragma unroll
    for (int o = 16; o; o >>= 1) v += __shfl_xor_sync(0xffffffffu, v, o);
    if (lane == 0) out[p] = v;
}

/* ---------------- host side ---------------- */
static inline unsigned gb(size_t n) { return (unsigned)((n + 255) / 256); }

static void conv(const int* src, const int* dst, int nN,
                 float* X, float* A, float* B, float* invs, float* w) {
    k_zero<<<gb(nN), 256>>>(invs, nN);
    k_deg<<<gb(NE), 256>>>(dst, invs, NE);
    k_rsqrt<<<gb(nN), 256>>>(invs, nN);
    k_edgew<<<gb(NE), 256>>>(src, dst, invs, w, NE);
    size_t n4 = (size_t)nN * 8;
    /* layer 1: X -> A */
    k_zero4<<<gb(n4), 256>>>((float4*)A, n4);
    k_scatter<<<gb((size_t)NE * 8), 256>>>(src, dst, w, X, A, NE);
    k_final<<<gb(n4), 256>>>((float4*)A, (const float4*)X, n4);
    /* layer 2: A -> B */
    k_zero4<<<gb(n4), 256>>>((float4*)B, n4);
    k_scatter<<<gb((size_t)NE * 8), 256>>>(src, dst, w, A, B, NE);
    k_final<<<gb(n4), 256>>>((float4*)B, (const float4*)X, n4);
}

extern "C" void kernel_launch(void* const* d_in, const int* in_sizes, int n_in,
                              void* d_out, int out_size) {
    const int*   dom   = (const int*)d_in[0];    /* [2, NE] */
    const int*   sep   = (const int*)d_in[1];    /* [3, 2, NE] */
    const float* aggru = (const float*)d_in[2];  /* [NTU, DIM] */
    const float* aggri = (const float*)d_in[3];  /* [NTI, DIM] */
    const float* domu  = (const float*)d_in[4];  /* [NDU, DIM] */
    const float* domi  = (const float*)d_in[5];  /* [NDI, DIM] */
    const int*   uid   = (const int*)d_in[6];    /* [NDU] */
    const int*   iid   = (const int*)d_in[7];    /* [NDI] */
    const void*  users = d_in[8];                /* [NQ] int32 or int64 */
    const void*  items = d_in[9];                /* [NQ] */
    float* out = (float*)d_out;

    float *X, *A, *B, *invs, *w, *light, *intra;
    cudaGetSymbolAddress((void**)&X, g_X);
    cudaGetSymbolAddress((void**)&A, g_A);
    cudaGetSymbolAddress((void**)&B, g_B);
    cudaGetSymbolAddress((void**)&invs, g_invs);
    cudaGetSymbolAddress((void**)&w, g_w);
    cudaGetSymbolAddress((void**)&light, g_light);
    cudaGetSymbolAddress((void**)&intra, g_intra);

    /* ---- intra-domain conv on 150K nodes ---- */
    k_copy4<<<gb((size_t)NDU * 8), 256>>>((float4*)X, (const float4*)domu, (size_t)NDU * 8);
    k_copy4<<<gb((size_t)NDI * 8), 256>>>((float4*)(X + (size_t)NDU * DIM),
                                          (const float4*)domi, (size_t)NDI * 8);
    conv(dom, dom + NE, NDOM, X, A, B, invs, w);
    k_copy4<<<gb((size_t)NDOM * 8), 256>>>((float4*)intra, (const float4*)B, (size_t)NDOM * 8);

    /* ---- inter-domain: 3 convs on 500K nodes, accumulate light ---- */
    k_zero4<<<gb((size_t)NDOM * 8), 256>>>((float4*)light, (size_t)NDOM * 8);
    k_copy4<<<gb((size_t)NTU * 8), 256>>>((float4*)X, (const float4*)aggru, (size_t)NTU * 8);
    k_copy4<<<gb((size_t)NTI * 8), 256>>>((float4*)(X + (size_t)NTU * DIM),
                                          (const float4*)aggri, (size_t)NTI * 8);
    for (int d = 0; d < 3; d++) {
        const int* s = sep + (size_t)d * 2 * NE;
        conv(s, s + NE, NALL, X, A, B, invs, w);
        k_accum<<<gb((size_t)NDOM * 8), 256>>>((float4*)light, (const float4*)B, uid, iid);
    }

    /* ---- final pairwise dots ---- */
    k_detect<<<1, 256>>>((const int*)users, NQ, 0);
    k_detect<<<1, 256>>>((const int*)items, NQ, 1);
    k_gamma<<<NQ / 8, 256>>>(users, items, light, intra, out);
}

// round 2
// speedup vs baseline: 1.0953x; 1.0953x over previous
#include <cuda_runtime.h>
#include <stdint.h>

#define NDU 60000
#define NDI 90000
#define NDOM (NDU + NDI)      /* 150000 */
#define NTU 200000
#define NTI 300000
#define NALL (NTU + NTI)      /* 500000 */
#define NE  2000000
#define DIM 32
#define NQ  8192
#define ALPHA 0.1f
#define BETA  0.9f

/* ---------------- static device scratch (no allocs allowed) ---------------- */
__device__ __align__(16) float g_X[(size_t)NALL * DIM];     /* 64 MB */
__device__ __align__(16) float g_A[(size_t)NALL * DIM];     /* 64 MB */
__device__ __align__(16) float g_B[(size_t)NALL * DIM];     /* 64 MB */
__device__ __align__(16) float g_light[(size_t)NDOM * DIM]; /* 19.2 MB */
__device__ __align__(16) float g_intra[(size_t)NDOM * DIM]; /* 19.2 MB */
__device__ float   g_invs[NALL];
__device__ float   g_w[NE];
__device__ uint8_t g_need[NALL];
__device__ int     g_f[2];   /* index-width flags: 1 => int64 */

/* ---------------- small helpers ---------------- */
__global__ void k_zero(float* p, int n) {
    int i = blockIdx.x * blockDim.x + threadIdx.x;
    if (i < n) p[i] = 0.f;
}
__global__ void k_zero4(float4* p, size_t n) {
    size_t i = (size_t)blockIdx.x * blockDim.x + threadIdx.x;
    if (i < n) p[i] = make_float4(0.f, 0.f, 0.f, 0.f);
}
__global__ void k_copy4(float4* d, const float4* __restrict__ s, size_t n) {
    size_t i = (size_t)blockIdx.x * blockDim.x + threadIdx.x;
    if (i < n) d[i] = s[i];
}
/* dst = ALPHA * src  (accumulator init; APPNP residual pre-added) */
__global__ void k_init4(float4* __restrict__ d, const float4* __restrict__ s, size_t n) {
    size_t i = (size_t)blockIdx.x * blockDim.x + threadIdx.x;
    if (i >= n) return;
    float4 v = s[i];
    d[i] = make_float4(ALPHA * v.x, ALPHA * v.y, ALPHA * v.z, ALPHA * v.w);
}

/* needed-node mask from uid/iid */
__global__ void k_need_clr(uint8_t* m, int n) {
    int i = blockIdx.x * blockDim.x + threadIdx.x;
    if (i < n) m[i] = 0;
}
__global__ void k_need_set(uint8_t* m, const int* __restrict__ uid, const int* __restrict__ iid) {
    int i = blockIdx.x * blockDim.x + threadIdx.x;
    if (i < NDU) m[uid[i]] = 1;
    else if (i < NDOM) m[NTU + iid[i - NDU]] = 1;
}
/* init only the needed rows of B with ALPHA*X */
__global__ void k_init_needed(float4* __restrict__ B, const float4* __restrict__ X,
                              const int* __restrict__ uid, const int* __restrict__ iid) {
    size_t i = (size_t)blockIdx.x * blockDim.x + threadIdx.x;
    if (i >= (size_t)NDOM * 8) return;
    int r = (int)(i >> 3);
    int c = (int)(i & 7);
    size_t row = (r < NDU) ? (size_t)uid[r] : (size_t)NTU + (size_t)iid[r - NDU];
    float4 v = X[row * 8 + c];
    B[row * 8 + c] = make_float4(ALPHA * v.x, ALPHA * v.y, ALPHA * v.z, ALPHA * v.w);
}

/* degree count (float, matches segment_sum of ones) */
__global__ void k_deg(const int* __restrict__ dst, float* deg, int nE) {
    int e = blockIdx.x * blockDim.x + threadIdx.x;
    if (e < nE) atomicAdd(&deg[dst[e]], 1.0f);
}
__global__ void k_rsqrt(float* d, int n) {
    int i = blockIdx.x * blockDim.x + threadIdx.x;
    if (i < n) d[i] = rsqrtf(fmaxf(d[i], 1.0f));
}
/* per-edge symmetric norm weight, with (1-ALPHA) folded in */
__global__ void k_edgew(const int* __restrict__ src, const int* __restrict__ dst,
                        const float* __restrict__ invs, float* __restrict__ w, int nE) {
    int e = blockIdx.x * blockDim.x + threadIdx.x;
    if (e < nE) w[e] = BETA * invs[src[e]] * invs[dst[e]];
}

/* scatter-add: 8 lanes/edge, float4 gather + red.v4 scatter.
   Accumulator must be pre-initialized to ALPHA*x; w carries the 0.9. */
template <bool MASKED>
__global__ void k_scatter(const int* __restrict__ src, const int* __restrict__ dst,
                          const float* __restrict__ w, const float* __restrict__ h,
                          float* __restrict__ agg, const uint8_t* __restrict__ need, int nE) {
    size_t t = (size_t)blockIdx.x * blockDim.x + threadIdx.x;
    int e = (int)(t >> 3);
    int lane = (int)(t & 7);
    if (e >= nE) return;
    int d = __ldg(dst + e);
    if (MASKED && !__ldg(need + d)) return;
    int s = __ldg(src + e);
    float ww = __ldg(w + e);
    float4 v = *(const float4*)(h + (size_t)s * DIM + lane * 4);
    float a0 = v.x * ww, a1 = v.y * ww, a2 = v.z * ww, a3 = v.w * ww;
    float* o = agg + (size_t)d * DIM + lane * 4;
    asm volatile("red.global.add.v4.f32 [%0], {%1,%2,%3,%4};"
                 :: "l"(o), "f"(a0), "f"(a1), "f"(a2), "f"(a3) : "memory");
}

/* light += h2 rows gathered at (uid, NTU+iid) */
__global__ void k_accum(float4* __restrict__ light, const float4* __restrict__ B,
                        const int* __restrict__ uid, const int* __restrict__ iid) {
    size_t i = (size_t)blockIdx.x * blockDim.x + threadIdx.x;
    if (i >= (size_t)NDOM * 8) return;
    int r = (int)(i >> 3);
    int c = (int)(i & 7);
    size_t sr = (r < NDU) ? (size_t)uid[r] : (size_t)NTU + (size_t)iid[r - NDU];
    float4 a = light[i], b = B[sr * 8 + c];
    a.x += b.x; a.y += b.y; a.z += b.z; a.w += b.w;
    light[i] = a;
}

/* detect int64 vs int32 index buffers */
__global__ void k_detect(const int* __restrict__ p, int nElems, int slot) {
    __shared__ int any;
    if (threadIdx.x == 0) any = 0;
    __syncthreads();
    for (int i = threadIdx.x; i < nElems / 2; i += blockDim.x)
        if (p[2 * i + 1] != 0) any = 1;
    __syncthreads();
    if (threadIdx.x == 0) g_f[slot] = (any == 0);
}

/* gamma[p] = dot(light_u, light_i)/9 + dot(intra_u, intra_i); one warp/pair */
__global__ void k_gamma(const void* __restrict__ users, const void* __restrict__ items,
                        const float* __restrict__ light, const float* __restrict__ intra,
                        float* __restrict__ out) {
    int p = (blockIdx.x * blockDim.x + threadIdx.x) >> 5;
    int lane = threadIdx.x & 31;
    if (p >= NQ) return;
    long long u  = g_f[0] ? ((const long long*)users)[p] : (long long)((const int*)users)[p];
    long long it = g_f[1] ? ((const long long*)items)[p] : (long long)((const int*)items)[p];
    size_t ur = (size_t)u * DIM + lane;
    size_t ir = ((size_t)NDU + (size_t)it) * DIM + lane;
    float v = light[ur] * light[ir] * (1.0f / 9.0f) + intra[ur] * intra[ir];
#pragma unroll
    for (int o = 16; o; o >>= 1) v += __shfl_xor_sync(0xffffffffu, v, o);
    if (lane == 0) out[p] = v;
}

/* ---------------- host side ---------------- */
static inline unsigned gb(size_t n) { return (unsigned)((n + 255) / 256); }

/* degrees + edge weights for one conv */
static void prep(const int* src, const int* dst, int nN, float* invs, float* w) {
    k_zero<<<gb(nN), 256>>>(invs, nN);
    k_deg<<<gb(NE), 256>>>(dst, invs, NE);
    k_rsqrt<<<gb(nN), 256>>>(invs, nN);
    k_edgew<<<gb(NE), 256>>>(src, dst, invs, w, NE);
}

extern "C" void kernel_launch(void* const* d_in, const int* in_sizes, int n_in,
                              void* d_out, int out_size) {
    const int*   dom   = (const int*)d_in[0];    /* [2, NE] */
    const int*   sep   = (const int*)d_in[1];    /* [3, 2, NE] */
    const float* aggru = (const float*)d_in[2];  /* [NTU, DIM] */
    const float* aggri = (const float*)d_in[3];  /* [NTI, DIM] */
    const float* domu  = (const float*)d_in[4];  /* [NDU, DIM] */
    const float* domi  = (const float*)d_in[5];  /* [NDI, DIM] */
    const int*   uid   = (const int*)d_in[6];    /* [NDU] */
    const int*   iid   = (const int*)d_in[7];    /* [NDI] */
    const void*  users = d_in[8];                /* [NQ] int32 or int64 */
    const void*  items = d_in[9];
    float* out = (float*)d_out;

    float *X, *A, *B, *invs, *w, *light, *intra;
    uint8_t* need;
    cudaGetSymbolAddress((void**)&X, g_X);
    cudaGetSymbolAddress((void**)&A, g_A);
    cudaGetSymbolAddress((void**)&B, g_B);
    cudaGetSymbolAddress((void**)&invs, g_invs);
    cudaGetSymbolAddress((void**)&w, g_w);
    cudaGetSymbolAddress((void**)&light, g_light);
    cudaGetSymbolAddress((void**)&intra, g_intra);
    cudaGetSymbolAddress((void**)&need, g_need);

    const size_t nd4 = (size_t)NDOM * 8;   /* float4 count, dom nodes */
    const size_t na4 = (size_t)NALL * 8;   /* float4 count, all nodes */

    /* needed-node mask (constant across the 3 inter convs) */
    k_need_clr<<<gb(NALL), 256>>>(need, NALL);
    k_need_set<<<gb(NDOM), 256>>>(need, uid, iid);
    k_detect<<<1, 256>>>((const int*)users, NQ, 0);
    k_detect<<<1, 256>>>((const int*)items, NQ, 1);

    /* ---- intra-domain conv (150K nodes); layer-2 scatters into g_intra ---- */
    k_copy4<<<gb((size_t)NDU * 8), 256>>>((float4*)X, (const float4*)domu, (size_t)NDU * 8);
    k_copy4<<<gb((size_t)NDI * 8), 256>>>((float4*)(X + (size_t)NDU * DIM),
                                          (const float4*)domi, (size_t)NDI * 8);
    prep(dom, dom + NE, NDOM, invs, w);
    k_init4<<<gb(nd4), 256>>>((float4*)A, (const float4*)X, nd4);
    k_scatter<false><<<gb((size_t)NE * 8), 256>>>(dom, dom + NE, w, X, A, 0, NE);
    k_init4<<<gb(nd4), 256>>>((float4*)intra, (const float4*)X, nd4);
    k_scatter<false><<<gb((size_t)NE * 8), 256>>>(dom, dom + NE, w, A, intra, 0, NE);

    /* ---- inter-domain: 3 convs on 500K nodes, accumulate light ---- */
    k_zero4<<<gb(nd4), 256>>>((float4*)light, nd4);
    k_copy4<<<gb((size_t)NTU * 8), 256>>>((float4*)X, (const float4*)aggru, (size_t)NTU * 8);
    k_copy4<<<gb((size_t)NTI * 8), 256>>>((float4*)(X + (size_t)NTU * DIM),
                                          (const float4*)aggri, (size_t)NTI * 8);
    for (int d = 0; d < 3; d++) {
        const int* s = sep + (size_t)d * 2 * NE;
        const int* t = s + NE;
        prep(s, t, NALL, invs, w);
        /* layer 1: full */
        k_init4<<<gb(na4), 256>>>((float4*)A, (const float4*)X, na4);
        k_scatter<false><<<gb((size_t)NE * 8), 256>>>(s, t, w, X, A, 0, NE);
        /* layer 2: only rows later gathered */
        k_init_needed<<<gb(nd4), 256>>>((float4*)B, (const float4*)X, uid, iid);
        k_scatter<true><<<gb((size_t)NE * 8), 256>>>(s, t, w, A, B, need, NE);
        k_accum<<<gb(nd4), 256>>>((float4*)light, (const float4*)B, uid, iid);
    }

    /* ---- final pairwise dots ---- */
    k_gamma<<<NQ / 8, 256>>>(users, items, light, intra, out);
}